// round 4
// baseline (speedup 1.0000x reference)
#include <cuda_runtime.h>
#include <math.h>

// ---------------------------------------------------------------------------
// Problem constants
// ---------------------------------------------------------------------------
#define N_TL   32768   // timeline sequences
#define T_TL   32      // timeline seq len
#define B_SZ   512     // batch
#define T_TX   64      // text seq len
#define E_DIM  50      // embedding
#define H_DIM  32      // rnn hidden

typedef unsigned long long ull;

// ---------------------------------------------------------------------------
// Scratch (static device globals; no runtime allocation allowed)
// ---------------------------------------------------------------------------
__device__ float g_h2[(size_t)N_TL * 64];   // timeline RNN final hidden [N, 2H]
__device__ float g_hn[(size_t)B_SZ * 64];   // text RNN final hidden [B, 2H]
__device__ float g_red[(size_t)B_SZ * 192]; // per-batch [mean | min | max]

// ---------------------------------------------------------------------------
// Weights in __constant__ — read through the uniform-const port (ULDC, floor 1)
// so weight broadcast costs NO smem-crossbar bandwidth and NO fma-pipe slots.
// Packed as 64-bit pairs {w[2p], w[2p+1]} for fma.rn.f32x2 operands.
//   cWi2[rnn][dir][unit][25]  (50 floats/row = 25 pairs)
//   cWh2[rnn][dir][unit][16]  (32 floats/row = 16 pairs)
// ---------------------------------------------------------------------------
__constant__ ull   cWi2[2][2][32][25];
__constant__ ull   cWh2[2][2][32][16];
__constant__ float cBi [2][2][32];
__constant__ float cBh [2][2][32];

// ---------------------------------------------------------------------------
// Helpers
// ---------------------------------------------------------------------------
union F4U { float4 v; ull u[2]; };
union F2U { float2 v; ull u;    };

__device__ __forceinline__ void fma2(ull& d, ull a, ull b) {
    asm("fma.rn.f32x2 %0, %1, %2, %0;" : "+l"(d) : "l"(a), "l"(b));
}
__device__ __forceinline__ float red2(ull a) {
    float lo, hi;
    asm("mov.b64 {%0,%1}, %2;" : "=f"(lo), "=f"(hi) : "l"(a));
    return lo + hi;
}
__device__ __forceinline__ float tanh_fast(float x) {
    x = fminf(fmaxf(x, -20.0f), 20.0f);
    float e = __expf(2.0f * x);
    return __fdividef(e - 1.0f, e + 1.0f);
}

// ===========================================================================
// Unified RNN kernel: lane = sequence.
//   Warp handles 32 sequences of ONE direction. Per step, per lane:
//     - x row (50 floats) loaded from global as 25 64-bit pairs (float4 path,
//       alignment branch on t parity — rows are 200B apart)
//     - h (32 floats) as 16 pairs from a PRIVATE smem column (each lane only
//       ever reads bytes it wrote itself -> warp-synchronous, zero syncs)
//     - 32 units x 41 FFMA2 with weight pairs from __constant__ (uniform port)
//   Grid: 148 blocks x 480 thr, one block per SM.
//     blocks [0,140): timeline warps (task = b*15+w, 2048 tasks)
//     blocks [140,148): text warps (4 per block = 32 tasks) on dedicated SMs
//       so their long serial chain (64 steps) isn't starved by timeline warps.
// ===========================================================================
#define TLB 140           // timeline blocks
#define WPB 15            // warps per block

__global__ __launch_bounds__(480)
void rnn_all_kernel(const float* __restrict__ Xtl, const float* __restrict__ Xtx)
{
    extern __shared__ float2 sh[];           // 512 float2 per warp (4KB)
    const int w    = threadIdx.x >> 5;
    const int lane = threadIdx.x & 31;
    float2* hb = sh + w * 512;               // [q(16)][lane(32)]

    int task, T, R;
    const float* X;
    float* outp;
    if (blockIdx.x < TLB) {
        task = blockIdx.x * WPB + w;
        if (task >= 2048) return;
        T = T_TL; R = 1; X = Xtl; outp = g_h2;
    } else {
        if (w >= 4) return;
        task = (blockIdx.x - TLB) * 4 + w;   // 0..31
        T = T_TX; R = 0; X = Xtx; outp = g_hn;
    }
    const int d   = task & 1;                // direction
    const int grp = task >> 1;
    const int n   = grp * 32 + lane;         // my sequence
    const float* xbase = X + (size_t)n * T * E_DIM;

    // init h = 0
#pragma unroll
    for (int q = 0; q < 16; q++) hb[q * 32 + lane] = make_float2(0.0f, 0.0f);

#pragma unroll 1
    for (int t = 0; t < T; t++) {
        const int rt = d ? (T - 1 - t) : t;
        const float* rp = xbase + rt * E_DIM;

        // ---- load x row as 25 pairs (rows alternate 16B alignment with rt)
        ull xr[25];
        if (rt & 1) {
            xr[0] = __ldg(reinterpret_cast<const ull*>(rp));
            const float4* p4 = reinterpret_cast<const float4*>(rp + 2);
#pragma unroll
            for (int i = 0; i < 12; i++) {
                F4U u; u.v = __ldg(p4 + i);
                xr[1 + 2 * i] = u.u[0];
                xr[2 + 2 * i] = u.u[1];
            }
        } else {
            const float4* p4 = reinterpret_cast<const float4*>(rp);
#pragma unroll
            for (int i = 0; i < 12; i++) {
                F4U u; u.v = __ldg(p4 + i);
                xr[2 * i]     = u.u[0];
                xr[2 * i + 1] = u.u[1];
            }
            xr[24] = __ldg(reinterpret_cast<const ull*>(rp + 48));
        }

        // ---- load h pairs (private column; written by this thread last step)
        ull hr[16];
#pragma unroll
        for (int q = 0; q < 16; q++) {
            F2U u; u.v = hb[q * 32 + lane];
            hr[q] = u.u;
        }

        // ---- 32 units, two at a time; weights via uniform-const port
#pragma unroll 1
        for (int j2 = 0; j2 < 16; j2++) {
            const int j0 = 2 * j2, j1 = 2 * j2 + 1;
            ull aA0 = 0ULL, aA1 = 0ULL, aB0 = 0ULL, aB1 = 0ULL;
#pragma unroll
            for (int p = 0; p < 25; p++) {
                const ull wA = cWi2[R][d][j0][p];
                const ull wB = cWi2[R][d][j1][p];
                if (p & 1) { fma2(aA1, xr[p], wA); fma2(aB1, xr[p], wB); }
                else       { fma2(aA0, xr[p], wA); fma2(aB0, xr[p], wB); }
            }
#pragma unroll
            for (int q = 0; q < 16; q++) {
                const ull wA = cWh2[R][d][j0][q];
                const ull wB = cWh2[R][d][j1][q];
                if (q & 1) { fma2(aA1, hr[q], wA); fma2(aB1, hr[q], wB); }
                else       { fma2(aA0, hr[q], wA); fma2(aB0, hr[q], wB); }
            }
            const float sA = red2(aA0) + red2(aA1) + cBi[R][d][j0] + cBh[R][d][j0];
            const float sB = red2(aB0) + red2(aB1) + cBi[R][d][j1] + cBh[R][d][j1];
            hb[j2 * 32 + lane] = make_float2(tanh_fast(sA), tanh_fast(sB));
        }
    }

    // ---- write final hidden: out[n][d*32 + 0..31]
    float2* op = reinterpret_cast<float2*>(outp + (size_t)n * 64 + d * 32);
#pragma unroll
    for (int q = 0; q < 16; q++) op[q] = hb[q * 32 + lane];
}

// ---------------------------------------------------------------------------
// Ragged segment mean/min/max over g_h2
// ---------------------------------------------------------------------------
__global__ void seg_reduce_kernel(const int* __restrict__ te)
{
    const int b = blockIdx.x;
    const int c = threadIdx.x;   // 0..63
    __shared__ int s_off;
    if (c == 0) {
        int o = 0;
        for (int i = 0; i < b; i++) o += te[i];
        s_off = o;
    }
    __syncthreads();
    const int cnt = te[b];
    const float* hp = g_h2 + (size_t)s_off * 64 + c;
    float sm = 0.0f, mn = 3.402823466e38f, mx = -3.402823466e38f;
    for (int r = 0; r < cnt; r++) {
        float v = hp[(size_t)r * 64];
        sm += v;
        mn = fminf(mn, v);
        mx = fmaxf(mx, v);
    }
    const float inv = (cnt > 0) ? __fdividef(1.0f, (float)cnt) : 0.0f;
    g_red[b * 192 + c]       = sm * inv;
    g_red[b * 192 + 64 + c]  = mn;
    g_red[b * 192 + 128 + c] = mx;
}

// ---------------------------------------------------------------------------
// Head: x = [h_n(64) | normal(49) | mean(64) | min(64) | max(64)] (305)
// ---------------------------------------------------------------------------
__global__ __launch_bounds__(128)
void head_kernel(const float* __restrict__ nf,
                 const float* __restrict__ fc1_w, const float* __restrict__ fc1_b,
                 const float* __restrict__ fc2_w, const float* __restrict__ fc2_b,
                 float* __restrict__ out)
{
    __shared__ float xv[305];
    __shared__ float yp[4];
    const int row  = blockIdx.x;
    const int tid  = threadIdx.x;
    const int w    = tid >> 5;
    const int lane = tid & 31;

    for (int i = tid; i < 305; i += 128) {
        float v;
        if (i < 64)        v = g_hn[(size_t)row * 64 + i];
        else if (i < 113)  v = nf[(size_t)row * 49 + (i - 64)];
        else               v = g_red[(size_t)row * 192 + (i - 113)];
        xv[i] = v;
    }
    __syncthreads();

    float acc = 0.0f;
#pragma unroll
    for (int uu = 0; uu < 8; uu++) {
        const int u = w * 8 + uu;
        const float* wr = fc1_w + (size_t)u * 305;
        float ps = 0.0f;
        for (int k = lane; k < 305; k += 32)
            ps = fmaf(__ldg(wr + k), xv[k], ps);
#pragma unroll
        for (int o = 16; o > 0; o >>= 1) ps += __shfl_xor_sync(0xffffffffu, ps, o);
        if (lane == 0) {
            float y = tanh_fast(ps + __ldg(fc1_b + u));
            acc = fmaf(y, __ldg(fc2_w + u), acc);
        }
    }
    if (lane == 0) yp[w] = acc;
    __syncthreads();
    if (tid == 0) {
        float z = yp[0] + yp[1] + yp[2] + yp[3] + __ldg(fc2_b);
        out[row] = __fdividef(1.0f, 1.0f + __expf(-z));
    }
}

// ---------------------------------------------------------------------------
// Launch. Runtime input-ordering detection (validated R2/R3).
// Constant weights uploaded via cudaMemcpyToSymbolAsync (D2D memcpy nodes,
// graph-capturable). No allocations anywhere.
// ---------------------------------------------------------------------------
extern "C" void kernel_launch(void* const* d_in, const int* in_sizes, int n_in,
                              void* d_out, int out_size)
{
    int base_r1, base_r2, base_fc, idx_te;
    if (in_sizes[3] == B_SZ) {          // setup_inputs order
        idx_te = 3;  base_r1 = 4;  base_r2 = 12; base_fc = 20;
    } else {                            // reference signature order
        base_r1 = 3; base_r2 = 11; base_fc = 19; idx_te = n_in - 1;
    }

    const float* nf  = (const float*)d_in[0];
    const float* tf  = (const float*)d_in[1];
    const float* ttf = (const float*)d_in[2];
    const int*   te  = (const int*)d_in[idx_te];
#define FPTR(i) ((const float*)d_in[(i)])

    // ---- upload weights to __constant__  (r: 0=rnn1/text, 1=rnn2/timeline)
    for (int r = 0; r < 2; r++) {
        const int base = r ? base_r2 : base_r1;
        for (int d = 0; d < 2; d++) {
            const int o = r * 2 + d;
            // input layout per rnn: wif, whf, bif, bhf, wib, whb, bib, bhb
            cudaMemcpyToSymbolAsync(cWi2, FPTR(base + 4 * d + 0),
                                    H_DIM * E_DIM * 4, (size_t)o * H_DIM * E_DIM * 4,
                                    cudaMemcpyDeviceToDevice, 0);
            cudaMemcpyToSymbolAsync(cWh2, FPTR(base + 4 * d + 1),
                                    H_DIM * H_DIM * 4, (size_t)o * H_DIM * H_DIM * 4,
                                    cudaMemcpyDeviceToDevice, 0);
            cudaMemcpyToSymbolAsync(cBi,  FPTR(base + 4 * d + 2),
                                    H_DIM * 4, (size_t)o * H_DIM * 4,
                                    cudaMemcpyDeviceToDevice, 0);
            cudaMemcpyToSymbolAsync(cBh,  FPTR(base + 4 * d + 3),
                                    H_DIM * 4, (size_t)o * H_DIM * 4,
                                    cudaMemcpyDeviceToDevice, 0);
        }
    }

    // ---- both RNNs in one launch: 148 blocks, one per SM
    const int dynsmem = WPB * 512 * sizeof(float2);   // 61440 B
    cudaFuncSetAttribute(rnn_all_kernel,
                         cudaFuncAttributeMaxDynamicSharedMemorySize, dynsmem);
    rnn_all_kernel<<<TLB + 8, WPB * 32, dynsmem>>>(ttf, tf);

    // ---- segment mean/min/max
    seg_reduce_kernel<<<B_SZ, 64>>>(te);

    // ---- head
    head_kernel<<<B_SZ, 128>>>(
        nf,
        FPTR(base_fc + 0), FPTR(base_fc + 1), FPTR(base_fc + 2), FPTR(base_fc + 3),
        (float*)d_out);
#undef FPTR
}

// round 5
// speedup vs baseline: 1.8843x; 1.8843x over previous
#include <cuda_runtime.h>
#include <math.h>

// ---------------------------------------------------------------------------
// Problem constants
// ---------------------------------------------------------------------------
#define N_TL   32768   // timeline sequences
#define T_TL   32      // timeline seq len
#define B_SZ   512     // batch
#define T_TX   64      // text seq len
#define E_DIM  50      // embedding
#define H_DIM  32      // rnn hidden

typedef unsigned long long ull;

// ---------------------------------------------------------------------------
// Scratch (static device globals; no runtime allocation allowed)
// ---------------------------------------------------------------------------
__device__ float g_h2[(size_t)N_TL * 64];   // timeline RNN final hidden [N, 2H]
__device__ float g_hn[(size_t)B_SZ * 64];   // text RNN final hidden [B, 2H]
__device__ float g_red[(size_t)B_SZ * 192]; // per-batch [mean | min | max]

// ---------------------------------------------------------------------------
// f32x2 helpers (correctness validated on sm_100a in R4: rel_err 6.4e-8)
// ---------------------------------------------------------------------------
__device__ __forceinline__ void fma2(ull& d, ull a, ull b) {
    asm("fma.rn.f32x2 %0, %1, %2, %0;" : "+l"(d) : "l"(a), "l"(b));
}
__device__ __forceinline__ ull add2(ull a, ull b) {
    ull r; asm("add.rn.f32x2 %0, %1, %2;" : "=l"(r) : "l"(a), "l"(b)); return r;
}
__device__ __forceinline__ ull pack2(float lo, float hi) {
    ull r; asm("mov.b64 %0, {%1, %2};" : "=l"(r) : "f"(lo), "f"(hi)); return r;
}
__device__ __forceinline__ void unpack2(ull a, float& lo, float& hi) {
    asm("mov.b64 {%0, %1}, %2;" : "=f"(lo), "=f"(hi) : "l"(a));
}
__device__ __forceinline__ float tanh_fast(float x) {
    x = fminf(fmaxf(x, -20.0f), 20.0f);
    float e = __expf(2.0f * x);
    return __fdividef(e - 1.0f, e + 1.0f);
}

// ===========================================================================
// Bidirectional RNN — R3 memory structure + FFMA2 unit-pair packing.
//   warp = one sequence, both directions:
//     lanes 0..15  : forward,  units (u, u+16), u = lane & 15
//     lanes 16..31 : backward, units (u, u+16)
//   smem per warp:
//     x duplicated: row t = 100 floats, element e stored as {v,v} at 2e.
//       Dual-row broadcast LDS.128 (fwd reads row t, bwd row T-1-t):
//       Δbank = (odd*100) mod 32 ∈ {4,12,20,28}, span 4 -> conflict-free.
//     h duplicated, double-parity: parity p at +p*136; fwd block at +0,
//       bwd at +68 (Δbank 4) -> the dual-half LDS.128 is conflict-free.
//   Weights: per-lane unit-pair packed, {W[u][k], W[u+16][k]}, in registers.
//   Math: 82 FFMA2 per lane-step covering both owned units (164 MACs).
// ===========================================================================
#define HPAR 136                      // floats per h parity buffer
#define WSTRIDE(T) ((T) * 100 + 2 * HPAR)   // floats per warp (16B-aligned)

template <int TSTEPS, int WARPS, bool TO_TL>
__global__ __launch_bounds__(WARPS * 32)
void rnn_kernel(const float* __restrict__ X,
                const float* __restrict__ wif, const float* __restrict__ whf,
                const float* __restrict__ bif, const float* __restrict__ bhf,
                const float* __restrict__ wib, const float* __restrict__ whb,
                const float* __restrict__ bib, const float* __restrict__ bhb)
{
    extern __shared__ __align__(16) float sh[];
    const int w    = threadIdx.x >> 5;
    const int lane = threadIdx.x & 31;
    const int half = lane >> 4;       // 0 = fwd, 1 = bwd
    const int u    = lane & 15;       // first owned unit
    const int dofs = half * 68;       // h-block offset for my direction

    float* xw = sh + w * WSTRIDE(TSTEPS);           // dup'd x [TSTEPS][100]
    float* hw = xw + TSTEPS * 100;                  // dup'd h [2][HPAR]

    const int n = blockIdx.x * WARPS + w;           // my sequence

    // ---- stage x, duplicated: element (t,e) -> float2{v,v} at slot t*50+e
    {
        const float* xg = X + (size_t)n * (TSTEPS * E_DIM);
        float2* xd = reinterpret_cast<float2*>(xw);
        for (int i = lane; i < TSTEPS * E_DIM; i += 32) {
            float v = __ldg(xg + i);
            xd[i] = make_float2(v, v);
        }
    }

    // ---- weights for my direction, units u and u+16, packed pairs
    const float* wi = half ? wib : wif;
    const float* wh = half ? whb : whf;
    const float* bi = half ? bib : bif;
    const float* bh = half ? bhb : bhf;

    ull Wi2[E_DIM];
#pragma unroll
    for (int e = 0; e < E_DIM; e++)
        Wi2[e] = pack2(__ldg(wi + u * E_DIM + e), __ldg(wi + (u + 16) * E_DIM + e));
    ull Wh2[H_DIM];
#pragma unroll
    for (int k = 0; k < H_DIM; k++)
        Wh2[k] = pack2(__ldg(wh + u * H_DIM + k), __ldg(wh + (u + 16) * H_DIM + k));
    const ull bias2 = pack2(__ldg(bi + u) + __ldg(bh + u),
                            __ldg(bi + u + 16) + __ldg(bh + u + 16));

    // ---- init h parity-0 = 0 (each lane zeroes its own dir's owned slots)
    {
        float2* hz = reinterpret_cast<float2*>(hw + dofs);
        hz[u]      = make_float2(0.0f, 0.0f);   // unit u      -> slot 2u
        hz[u + 16] = make_float2(0.0f, 0.0f);   // unit u+16   -> slot 2u+32
    }
    __syncwarp();

    float h0 = 0.0f, h1 = 0.0f;

#pragma unroll 1
    for (int s = 0; s < TSTEPS; s++) {
        const int p   = s & 1;
        const int row = half ? (TSTEPS - 1 - s) : s;

        const float4* xr = reinterpret_cast<const float4*>(xw + row * 100);
        const float4* hr = reinterpret_cast<const float4*>(hw + p * HPAR + dofs);

        ull a0 = bias2, a1 = 0ULL, a2 = 0ULL, a3 = 0ULL;

        // x part: 25 LDS.128 -> 50 packed pairs -> 50 FFMA2
#pragma unroll
        for (int q = 0; q < 25; q++) {
            float4 v = xr[q];
            ull lo, hi;
            asm("mov.b64 %0, {%2, %3}; mov.b64 %1, {%4, %5};"
                : "=l"(lo), "=l"(hi) : "f"(v.x), "f"(v.y), "f"(v.z), "f"(v.w));
            if (q & 1) { fma2(a2, lo, Wi2[2 * q]); fma2(a3, hi, Wi2[2 * q + 1]); }
            else       { fma2(a0, lo, Wi2[2 * q]); fma2(a1, hi, Wi2[2 * q + 1]); }
        }
        // h part: 16 LDS.128 -> 32 packed pairs -> 32 FFMA2
#pragma unroll
        for (int q = 0; q < 16; q++) {
            float4 v = hr[q];
            ull lo, hi;
            asm("mov.b64 %0, {%2, %3}; mov.b64 %1, {%4, %5};"
                : "=l"(lo), "=l"(hi) : "f"(v.x), "f"(v.y), "f"(v.z), "f"(v.w));
            if (q & 1) { fma2(a2, lo, Wh2[2 * q]); fma2(a3, hi, Wh2[2 * q + 1]); }
            else       { fma2(a0, lo, Wh2[2 * q]); fma2(a1, hi, Wh2[2 * q + 1]); }
        }

        float sA, sB;
        unpack2(add2(add2(a0, a1), add2(a2, a3)), sA, sB);
        h0 = tanh_fast(sA);
        h1 = tanh_fast(sB);

        // write dup'd h to parity p^1
        {
            float2* hd = reinterpret_cast<float2*>(hw + (p ^ 1) * HPAR + dofs);
            hd[u]      = make_float2(h0, h0);
            hd[u + 16] = make_float2(h1, h1);
        }
        __syncwarp();
    }

    // ---- final hidden -> out[n][half*32 + {u, u+16}] (coalesced across warp)
    float* outp = TO_TL ? g_h2 : g_hn;
    outp[(size_t)n * 64 + half * 32 + u]      = h0;
    outp[(size_t)n * 64 + half * 32 + u + 16] = h1;
}

// ---------------------------------------------------------------------------
// Ragged segment mean/min/max over g_h2 (validated R2/R3)
// ---------------------------------------------------------------------------
__global__ void seg_reduce_kernel(const int* __restrict__ te)
{
    const int b = blockIdx.x;
    const int c = threadIdx.x;   // 0..63
    __shared__ int s_off;
    if (c == 0) {
        int o = 0;
        for (int i = 0; i < b; i++) o += te[i];
        s_off = o;
    }
    __syncthreads();
    const int cnt = te[b];
    const float* hp = g_h2 + (size_t)s_off * 64 + c;
    float sm = 0.0f, mn = 3.402823466e38f, mx = -3.402823466e38f;
    for (int r = 0; r < cnt; r++) {
        float v = hp[(size_t)r * 64];
        sm += v;
        mn = fminf(mn, v);
        mx = fmaxf(mx, v);
    }
    const float inv = (cnt > 0) ? __fdividef(1.0f, (float)cnt) : 0.0f;
    g_red[b * 192 + c]       = sm * inv;
    g_red[b * 192 + 64 + c]  = mn;
    g_red[b * 192 + 128 + c] = mx;
}

// ---------------------------------------------------------------------------
// Head (validated R3): one block per batch row, coalesced fc1 dots.
// ---------------------------------------------------------------------------
__global__ __launch_bounds__(128)
void head_kernel(const float* __restrict__ nf,
                 const float* __restrict__ fc1_w, const float* __restrict__ fc1_b,
                 const float* __restrict__ fc2_w, const float* __restrict__ fc2_b,
                 float* __restrict__ out)
{
    __shared__ float xv[305];
    __shared__ float yp[4];
    const int row  = blockIdx.x;
    const int tid  = threadIdx.x;
    const int w    = tid >> 5;
    const int lane = tid & 31;

    for (int i = tid; i < 305; i += 128) {
        float v;
        if (i < 64)        v = g_hn[(size_t)row * 64 + i];
        else if (i < 113)  v = nf[(size_t)row * 49 + (i - 64)];
        else               v = g_red[(size_t)row * 192 + (i - 113)];
        xv[i] = v;
    }
    __syncthreads();

    float acc = 0.0f;
#pragma unroll
    for (int uu = 0; uu < 8; uu++) {
        const int u = w * 8 + uu;
        const float* wr = fc1_w + (size_t)u * 305;
        float ps = 0.0f;
        for (int k = lane; k < 305; k += 32)
            ps = fmaf(__ldg(wr + k), xv[k], ps);
#pragma unroll
        for (int o = 16; o > 0; o >>= 1) ps += __shfl_xor_sync(0xffffffffu, ps, o);
        if (lane == 0) {
            float y = tanh_fast(ps + __ldg(fc1_b + u));
            acc = fmaf(y, __ldg(fc2_w + u), acc);
        }
    }
    if (lane == 0) yp[w] = acc;
    __syncthreads();
    if (tid == 0) {
        float z = yp[0] + yp[1] + yp[2] + yp[3] + __ldg(fc2_b);
        out[row] = __fdividef(1.0f, 1.0f + __expf(-z));
    }
}

// ---------------------------------------------------------------------------
// Launch. Runtime input-ordering detection (validated R2-R4).
// Pure kernel launches — graph-capturable, allocation-free.
// ---------------------------------------------------------------------------
extern "C" void kernel_launch(void* const* d_in, const int* in_sizes, int n_in,
                              void* d_out, int out_size)
{
    int base_r1, base_r2, base_fc, idx_te;
    if (in_sizes[3] == B_SZ) {          // setup_inputs order
        idx_te = 3;  base_r1 = 4;  base_r2 = 12; base_fc = 20;
    } else {                            // reference signature order
        base_r1 = 3; base_r2 = 11; base_fc = 19; idx_te = n_in - 1;
    }

    const float* nf  = (const float*)d_in[0];
    const float* tf  = (const float*)d_in[1];
    const float* ttf = (const float*)d_in[2];
    const int*   te  = (const int*)d_in[idx_te];
#define FPTR(i) ((const float*)d_in[(i)])

    // Timeline RNN: 4096 blocks x 8 warps, warp = one sequence.
    {
        const int smem = WSTRIDE(T_TL) * 8 * sizeof(float);   // 111,104 B
        cudaFuncSetAttribute((const void*)rnn_kernel<T_TL, 8, true>,
                             cudaFuncAttributeMaxDynamicSharedMemorySize, smem);
        rnn_kernel<T_TL, 8, true><<<N_TL / 8, 256, smem>>>(
            ttf,
            FPTR(base_r2 + 0), FPTR(base_r2 + 1), FPTR(base_r2 + 2), FPTR(base_r2 + 3),
            FPTR(base_r2 + 4), FPTR(base_r2 + 5), FPTR(base_r2 + 6), FPTR(base_r2 + 7));
    }

    // Text RNN: 128 blocks x 4 warps (512 sequences, T=64).
    {
        const int smem = WSTRIDE(T_TX) * 4 * sizeof(float);   // 106,752 B
        cudaFuncSetAttribute((const void*)rnn_kernel<T_TX, 4, false>,
                             cudaFuncAttributeMaxDynamicSharedMemorySize, smem);
        rnn_kernel<T_TX, 4, false><<<B_SZ / 4, 128, smem>>>(
            tf,
            FPTR(base_r1 + 0), FPTR(base_r1 + 1), FPTR(base_r1 + 2), FPTR(base_r1 + 3),
            FPTR(base_r1 + 4), FPTR(base_r1 + 5), FPTR(base_r1 + 6), FPTR(base_r1 + 7));
    }

    // Segment mean/min/max.
    seg_reduce_kernel<<<B_SZ, 64>>>(te);

    // Head.
    head_kernel<<<B_SZ, 128>>>(
        nf,
        FPTR(base_fc + 0), FPTR(base_fc + 1), FPTR(base_fc + 2), FPTR(base_fc + 3),
        (float*)d_out);
#undef FPTR
}

// round 7
// speedup vs baseline: 2.8939x; 1.5358x over previous
#include <cuda_runtime.h>
#include <math.h>

// ---------------------------------------------------------------------------
// Problem constants
// ---------------------------------------------------------------------------
#define N_TL   32768   // timeline sequences
#define T_TL   32      // timeline seq len
#define B_SZ   512     // batch
#define T_TX   64      // text seq len
#define E_DIM  50      // embedding
#define H_DIM  32      // rnn hidden

typedef unsigned long long ull;

// ---------------------------------------------------------------------------
// Scratch (static device globals; no runtime allocation allowed)
// ---------------------------------------------------------------------------
__device__ float g_h2[(size_t)N_TL * 64];   // timeline RNN final hidden [N, 2H]
__device__ float g_hn[(size_t)B_SZ * 64];   // text RNN final hidden [B, 2H]
__device__ float g_red[(size_t)B_SZ * 192]; // per-batch [mean | min | max]

// ---------------------------------------------------------------------------
// f32x2 helpers (validated on sm_100a in R4/R5) + hardware tanh (MUFU.TANH)
// ---------------------------------------------------------------------------
__device__ __forceinline__ void fma2(ull& d, ull a, ull b) {
    asm("fma.rn.f32x2 %0, %1, %2, %0;" : "+l"(d) : "l"(a), "l"(b));
}
__device__ __forceinline__ ull pack2(float lo, float hi) {
    ull r; asm("mov.b64 %0, {%1, %2};" : "=l"(r) : "f"(lo), "f"(hi)); return r;
}
__device__ __forceinline__ float red2(ull a) {
    float lo, hi;
    asm("mov.b64 {%0, %1}, %2;" : "=f"(lo), "=f"(hi) : "l"(a));
    return lo + hi;
}
__device__ __forceinline__ float tanh_hw(float x) {
    float y; asm("tanh.approx.f32 %0, %1;" : "=f"(y) : "f"(x)); return y;
}
__device__ __forceinline__ float tanh_acc(float x) {   // head-precision tanh
    x = fminf(fmaxf(x, -20.0f), 20.0f);
    float e = __expf(2.0f * x);
    return __fdividef(e - 1.0f, e + 1.0f);
}

// ===========================================================================
// TIMELINE RNN — R3's validated memory structure (warp = one sequence, both
// directions; x staged in smem rows of 56; h dual-parity broadcast buffer;
// 21 LDS.128 per step, no duplication) with the inner product switched to
// K-packed FFMA2: the float4 LDS yields {v.x,v.y},{v.z,v.w} pairs that
// multiply weight pairs {W[u][2q],W[u][2q+1]} held in registers.
//   Per lane-step: 2 units x (26 + 16) = 84 FFMA2 (was 164 FFMA).
//   tanh via single MUFU.TANH (was ex2+rcp).
// Persistent grid-stride, 592 blocks x 2 warps = exactly 4 blocks/SM.
// ===========================================================================
#define XROW 56
#define HSTR 36   // bwd h block offset inside a parity buffer

__global__ __launch_bounds__(64, 4)
void timeline_rnn_kernel(const float* __restrict__ X,
                         const float* __restrict__ wif, const float* __restrict__ whf,
                         const float* __restrict__ bif, const float* __restrict__ bhf,
                         const float* __restrict__ wib, const float* __restrict__ whb,
                         const float* __restrict__ bib, const float* __restrict__ bhb)
{
    __shared__ __align__(16) float xs[2][2][T_TL * XROW]; // [warp][buf][row*56]
    __shared__ __align__(16) float hsm[2][2 * 72];        // [warp][parity*72 + dir*36 + unit]

    const int lane   = threadIdx.x & 31;
    const int wlocal = threadIdx.x >> 5;          // 0..1
    const int half   = lane >> 4;                 // 0 = fwd, 1 = bwd
    const int u      = lane & 15;                 // first owned unit
    const int dofs   = half * HSTR;

    const int gwarp  = blockIdx.x * 2 + wlocal;
    const int stride = gridDim.x * 2;

    // ---- weights for this lane's direction, rows u and u+16, K-packed pairs
    const float* wi = half ? wib : wif;
    const float* wh = half ? whb : whf;
    const float* bi = half ? bib : bif;
    const float* bh = half ? bhb : bhf;

    ull WiA[26], WiB[26];
#pragma unroll
    for (int q = 0; q < 25; q++) {
        WiA[q] = pack2(__ldg(wi + u * E_DIM + 2 * q), __ldg(wi + u * E_DIM + 2 * q + 1));
        WiB[q] = pack2(__ldg(wi + (u + 16) * E_DIM + 2 * q), __ldg(wi + (u + 16) * E_DIM + 2 * q + 1));
    }
    WiA[25] = 0ULL; WiB[25] = 0ULL;               // covers zero-padded cols 50,51
    ull WhA[16], WhB[16];
#pragma unroll
    for (int q = 0; q < 16; q++) {
        WhA[q] = pack2(__ldg(wh + u * H_DIM + 2 * q), __ldg(wh + u * H_DIM + 2 * q + 1));
        WhB[q] = pack2(__ldg(wh + (u + 16) * H_DIM + 2 * q), __ldg(wh + (u + 16) * H_DIM + 2 * q + 1));
    }
    const float biasA = __ldg(bi + u)      + __ldg(bh + u);
    const float biasB = __ldg(bi + u + 16) + __ldg(bh + u + 16);

    float* xw = &xs[wlocal][0][0];
    float* hw = &hsm[wlocal][0];

    // ---- prefetch first sequence into buffer 0 (zero the 50..55 pad!)
    int n = gwarp;
    if (n < N_TL) {
        const float* xg = X + (size_t)n * (T_TL * E_DIM);
        for (int i = lane; i < T_TL * XROW; i += 32) {
            int r = i / XROW, c = i - r * XROW;
            xw[i] = (c < E_DIM) ? __ldg(xg + r * E_DIM + c) : 0.0f;
        }
    }
    int buf = 0;

    for (; n < N_TL; n += stride) {
        // prefetch next sequence into the other buffer (overlaps with compute)
        int n2 = n + stride;
        if (n2 < N_TL) {
            const float* xg = X + (size_t)n2 * (T_TL * E_DIM);
            float* xd = xw + (buf ^ 1) * (T_TL * XROW);
            for (int i = lane; i < T_TL * XROW; i += 32) {
                int r = i / XROW, c = i - r * XROW;
                xd[i] = (c < E_DIM) ? __ldg(xg + r * E_DIM + c) : 0.0f;
            }
        }
        __syncwarp();

        // init h parity-0
        hw[dofs + u]      = 0.0f;
        hw[dofs + u + 16] = 0.0f;
        __syncwarp();

        const float* xb = xw + buf * (T_TL * XROW);
        float h0 = 0.0f, h1 = 0.0f;

#pragma unroll 1
        for (int s = 0; s < T_TL; s++) {
            const int p   = s & 1;
            const int row = half ? (T_TL - 1 - s) : s;   // per-half x row
            const float4* xr = reinterpret_cast<const float4*>(xb + row * XROW);
            const float4* hr = reinterpret_cast<const float4*>(hw + p * 72 + dofs);

            ull aA0 = pack2(biasA, 0.0f), aA1 = 0ULL;    // unit u
            ull aB0 = pack2(biasB, 0.0f), aB1 = 0ULL;    // unit u+16

            // x part: 13 LDS.128 -> 26 native pairs -> 52 FFMA2
#pragma unroll
            for (int q = 0; q < 13; q++) {
                float4 v = xr[q];
                ull lo = pack2(v.x, v.y);
                ull hi = pack2(v.z, v.w);
                fma2(aA0, lo, WiA[2 * q]);
                fma2(aA1, hi, WiA[2 * q + 1]);
                fma2(aB0, lo, WiB[2 * q]);
                fma2(aB1, hi, WiB[2 * q + 1]);
            }
            // h part: 8 LDS.128 -> 16 native pairs -> 32 FFMA2
#pragma unroll
            for (int q = 0; q < 8; q++) {
                float4 v = hr[q];
                ull lo = pack2(v.x, v.y);
                ull hi = pack2(v.z, v.w);
                fma2(aA0, lo, WhA[2 * q]);
                fma2(aA1, hi, WhA[2 * q + 1]);
                fma2(aB0, lo, WhB[2 * q]);
                fma2(aB1, hi, WhB[2 * q + 1]);
            }

            h0 = tanh_hw(red2(aA0) + red2(aA1));
            h1 = tanh_hw(red2(aB0) + red2(aB1));
            hw[(p ^ 1) * 72 + dofs + u]      = h0;
            hw[(p ^ 1) * 72 + dofs + u + 16] = h1;
            __syncwarp();
        }

        // final hidden -> [n, dir*32 + unit]
        g_h2[(size_t)n * 64 + half * 32 + u]      = h0;
        g_h2[(size_t)n * 64 + half * 32 + u + 16] = h1;
        __syncwarp();  // reads of `buf` done before next iter restages it
        buf ^= 1;
    }
}

// ===========================================================================
// TEXT RNN (1/32 of the work) — R3 design verbatim + hardware tanh.
// ===========================================================================
template <int TSTEPS, int PAIRS>
__global__ __launch_bounds__(PAIRS * 64)
void text_rnn_kernel(const float* __restrict__ X,
                     const float* __restrict__ wif, const float* __restrict__ whf,
                     const float* __restrict__ bif, const float* __restrict__ bhf,
                     const float* __restrict__ wib, const float* __restrict__ whb,
                     const float* __restrict__ bib, const float* __restrict__ bhb,
                     int nseq)
{
    __shared__ __align__(16) float xsl[PAIRS][TSTEPS][52];
    __shared__ __align__(16) float hbuf[2][PAIRS * 2][32];

    const int tid  = threadIdx.x;
    const int w    = tid >> 5;
    const int lane = tid & 31;
    const int p    = w >> 1;
    const int dir  = w & 1;
    const int nn   = blockIdx.x * PAIRS + p;

    {
        const int q = tid - p * 64;
        const float* xg = X + (size_t)nn * (TSTEPS * E_DIM);
        for (int i = q; i < TSTEPS * 52; i += 64) {
            int t = i / 52;
            int e = i - t * 52;
            xsl[p][t][e] = (e < E_DIM) ? xg[t * E_DIM + e] : 0.0f;
        }
    }
    __syncthreads();

    const float* wi = dir ? wib : wif;
    const float* wh = dir ? whb : whf;
    const float* bi = dir ? bib : bif;
    const float* bh = dir ? bhb : bhf;

    float Wi[52];
#pragma unroll
    for (int e = 0; e < E_DIM; e++) Wi[e] = __ldg(&wi[lane * E_DIM + e]);
    Wi[50] = 0.0f; Wi[51] = 0.0f;
    float Wh[32];
#pragma unroll
    for (int k = 0; k < H_DIM; k++) Wh[k] = __ldg(&wh[lane * H_DIM + k]);
    const float bias = __ldg(&bi[lane]) + __ldg(&bh[lane]);

    float h = 0.0f;
#pragma unroll 1
    for (int s = 0; s < TSTEPS; s++) {
        const int t   = dir ? (TSTEPS - 1 - s) : s;
        const int par = s & 1;
        hbuf[par][w][lane] = h;
        __syncwarp();

        float a0 = bias, a1 = 0.0f, a2 = 0.0f, a3 = 0.0f;
        const float4* xr = reinterpret_cast<const float4*>(xsl[p][t]);
#pragma unroll
        for (int q4 = 0; q4 < 13; q4++) {
            float4 v = xr[q4];
            a0 = fmaf(v.x, Wi[4 * q4 + 0], a0);
            a1 = fmaf(v.y, Wi[4 * q4 + 1], a1);
            a2 = fmaf(v.z, Wi[4 * q4 + 2], a2);
            a3 = fmaf(v.w, Wi[4 * q4 + 3], a3);
        }
        const float4* hr = reinterpret_cast<const float4*>(hbuf[par][w]);
#pragma unroll
        for (int q4 = 0; q4 < 8; q4++) {
            float4 v = hr[q4];
            a0 = fmaf(v.x, Wh[4 * q4 + 0], a0);
            a1 = fmaf(v.y, Wh[4 * q4 + 1], a1);
            a2 = fmaf(v.z, Wh[4 * q4 + 2], a2);
            a3 = fmaf(v.w, Wh[4 * q4 + 3], a3);
        }
        h = tanh_hw((a0 + a1) + (a2 + a3));
    }

    if (nn < nseq)
        g_hn[(size_t)nn * 64 + dir * 32 + lane] = h;
}

// ---------------------------------------------------------------------------
// Ragged segment mean/min/max over g_h2 (validated R2-R5)
// ---------------------------------------------------------------------------
__global__ void seg_reduce_kernel(const int* __restrict__ te)
{
    const int b = blockIdx.x;
    const int c = threadIdx.x;   // 0..63
    __shared__ int s_off;
    if (c == 0) {
        int o = 0;
        for (int i = 0; i < b; i++) o += te[i];
        s_off = o;
    }
    __syncthreads();
    const int cnt = te[b];
    const float* hp = g_h2 + (size_t)s_off * 64 + c;
    float sm = 0.0f, mn = 3.402823466e38f, mx = -3.402823466e38f;
    for (int r = 0; r < cnt; r++) {
        float v = hp[(size_t)r * 64];
        sm += v;
        mn = fminf(mn, v);
        mx = fmaxf(mx, v);
    }
    const float inv = (cnt > 0) ? __fdividef(1.0f, (float)cnt) : 0.0f;
    g_red[b * 192 + c]       = sm * inv;
    g_red[b * 192 + 64 + c]  = mn;
    g_red[b * 192 + 128 + c] = mx;
}

// ---------------------------------------------------------------------------
// Head (validated R3): one block per batch row, coalesced fc1 dots.
// Keeps the accurate tanh (single use per row; precision headroom).
// ---------------------------------------------------------------------------
__global__ __launch_bounds__(128)
void head_kernel(const float* __restrict__ nf,
                 const float* __restrict__ fc1_w, const float* __restrict__ fc1_b,
                 const float* __restrict__ fc2_w, const float* __restrict__ fc2_b,
                 float* __restrict__ out)
{
    __shared__ float xv[305];
    __shared__ float yp[4];
    const int row  = blockIdx.x;
    const int tid  = threadIdx.x;
    const int w    = tid >> 5;
    const int lane = tid & 31;

    for (int i = tid; i < 305; i += 128) {
        float v;
        if (i < 64)        v = g_hn[(size_t)row * 64 + i];
        else if (i < 113)  v = nf[(size_t)row * 49 + (i - 64)];
        else               v = g_red[(size_t)row * 192 + (i - 113)];
        xv[i] = v;
    }
    __syncthreads();

    float acc = 0.0f;
#pragma unroll
    for (int uu = 0; uu < 8; uu++) {
        const int u = w * 8 + uu;
        const float* wr = fc1_w + (size_t)u * 305;
        float ps = 0.0f;
        for (int k = lane; k < 305; k += 32)
            ps = fmaf(__ldg(wr + k), xv[k], ps);
#pragma unroll
        for (int o = 16; o > 0; o >>= 1) ps += __shfl_xor_sync(0xffffffffu, ps, o);
        if (lane == 0) {
            float y = tanh_acc(ps + __ldg(fc1_b + u));
            acc = fmaf(y, __ldg(fc2_w + u), acc);
        }
    }
    if (lane == 0) yp[w] = acc;
    __syncthreads();
    if (tid == 0) {
        float z = yp[0] + yp[1] + yp[2] + yp[3] + __ldg(fc2_b);
        out[row] = __fdividef(1.0f, 1.0f + __expf(-z));
    }
}

// ---------------------------------------------------------------------------
// Launch. Runtime input-ordering detection (validated R2-R5).
// Pure kernel launches — graph-capturable, allocation-free.
// ---------------------------------------------------------------------------
extern "C" void kernel_launch(void* const* d_in, const int* in_sizes, int n_in,
                              void* d_out, int out_size)
{
    int base_r1, base_r2, base_fc, idx_te;
    if (in_sizes[3] == B_SZ) {          // setup_inputs order
        idx_te = 3;  base_r1 = 4;  base_r2 = 12; base_fc = 20;
    } else {                            // reference signature order
        base_r1 = 3; base_r2 = 11; base_fc = 19; idx_te = n_in - 1;
    }

    const float* nf  = (const float*)d_in[0];
    const float* tf  = (const float*)d_in[1];
    const float* ttf = (const float*)d_in[2];
    const int*   te  = (const int*)d_in[idx_te];
#define FPTR(i) ((const float*)d_in[(i)])

    // Timeline RNN: persistent warps, 592 blocks (exactly 4/SM) x 2 warps.
    timeline_rnn_kernel<<<592, 64>>>(
        ttf,
        FPTR(base_r2 + 0), FPTR(base_r2 + 1), FPTR(base_r2 + 2), FPTR(base_r2 + 3),
        FPTR(base_r2 + 4), FPTR(base_r2 + 5), FPTR(base_r2 + 6), FPTR(base_r2 + 7));

    // Text RNN: 512 seqs, 2 per block (4 warps), 256 blocks.
    text_rnn_kernel<T_TX, 2><<<B_SZ / 2, 128>>>(
        tf,
        FPTR(base_r1 + 0), FPTR(base_r1 + 1), FPTR(base_r1 + 2), FPTR(base_r1 + 3),
        FPTR(base_r1 + 4), FPTR(base_r1 + 5), FPTR(base_r1 + 6), FPTR(base_r1 + 7),
        B_SZ);

    // Segment mean/min/max.
    seg_reduce_kernel<<<B_SZ, 64>>>(te);

    // Head.
    head_kernel<<<B_SZ, 128>>>(
        nf,
        FPTR(base_fc + 0), FPTR(base_fc + 1), FPTR(base_fc + 2), FPTR(base_fc + 3),
        (float*)d_out);
#undef FPTR
}